// round 1
// baseline (speedup 1.0000x reference)
#include <cuda_runtime.h>
#include <cstdint>

#define TOTAL_LEN 0.078f
#define NGRID 129
#define NIN 72
#define NY 17
#define NMIR 57          // 129 - 72
#define BROWS 65536
#define NOUT 1224        // 72*17
#define OUT_STRIDE 2193  // 129*17
#define KDIM 100
#define KCHUNK 56        // K padded to 112 = 2*56, 56 = 7 k-steps of 8

// Scratch (device globals: allocation-free per harness rules)
__device__ float g_H2T[KDIM * BROWS];   // layer-2 activations, [k][row], tf32-rounded
__device__ int   g_col1[NMIR];
__device__ float g_w[NMIR];
__device__ int   g_near[NMIR];
__device__ int   g_colnear[NMIR];

__device__ __forceinline__ float tf32_rna(float f) {
    uint32_t r;
    asm("cvt.rna.tf32.f32 %0, %1;" : "=r"(r) : "f"(f));
    return __uint_as_float(r);
}

__device__ __forceinline__ float sigmoid_fast(float z) {
    return 1.0f / (1.0f + __expf(-z));
}

// ---------------------------------------------------------------------------
// Kernel P: mirror interpolation parameters (batch-independent, 57 columns)
// ---------------------------------------------------------------------------
__global__ void prep_kernel(const float* __restrict__ xs) {
    __shared__ float sxs[NGRID];
    int t = threadIdx.x;
    for (int i = t; i < NGRID; i += blockDim.x) sxs[i] = xs[i];
    __syncthreads();
    if (t < NMIR) {
        float x_pos = TOTAL_LEN - sxs[NIN + t];
        g_near[t] = ((TOTAL_LEN - x_pos) < 0.02f) ? 1 : 0;
        // argmin |x_pos - xs| (first minimum, like jnp.argmin), clipped to NIN-1
        int best = 0; float bd = fabsf(x_pos - sxs[0]);
        for (int i = 1; i < NGRID; i++) {
            float d = fabsf(x_pos - sxs[i]);
            if (d < bd) { bd = d; best = i; }
        }
        if (best > NIN - 1) best = NIN - 1;
        g_colnear[t] = best;
        // searchsorted(xs, x_pos, 'right') - 1 == count(xs <= x_pos) - 1
        int cnt = 0;
        for (int i = 0; i < NGRID; i++) cnt += (sxs[i] <= x_pos) ? 1 : 0;
        int c1 = cnt - 1;
        if (c1 < 0) c1 = 0;
        if (c1 > NIN - 2) c1 = NIN - 2;
        g_col1[t] = c1;
        g_w[t] = (sxs[c1 + 1] - x_pos) / (sxs[c1 + 1] - sxs[c1]);
    }
}

// ---------------------------------------------------------------------------
// Kernel A: layers 1+2 (fp32), store H2^T [k][row] rounded to tf32
// ---------------------------------------------------------------------------
__global__ void mlp12_kernel(const float* __restrict__ x,
                             const float* __restrict__ W1, const float* __restrict__ b1,
                             const float* __restrict__ W2, const float* __restrict__ b2) {
    __shared__ float sW1[10], sb1[10], sW2[1000], sb2[100];
    int t = threadIdx.x;
    if (t < 10) { sW1[t] = W1[t]; sb1[t] = b1[t]; }
    for (int i = t; i < 1000; i += blockDim.x) sW2[i] = W2[i];
    if (t < 100) sb2[t] = b2[t];
    __syncthreads();

    int row = blockIdx.x * blockDim.x + t;
    float xv = x[row];
    float h1[10];
#pragma unroll
    for (int j = 0; j < 10; j++)
        h1[j] = sigmoid_fast(fmaf(xv, sW1[j], sb1[j]));

#pragma unroll 4
    for (int i = 0; i < 100; i++) {
        float s = sb2[i];
#pragma unroll
        for (int j = 0; j < 10; j++) s = fmaf(h1[j], sW2[j * 100 + i], s);
        g_H2T[i * BROWS + row] = tf32_rna(sigmoid_fast(s));
    }
}

// ---------------------------------------------------------------------------
// Kernel B: C = sigmoid(H2 @ W3 + b3) via mma.sync m16n8k8 tf32
// BM=128, BN=72, K padded 112 (2 chunks of 56). 192 threads = 6 warps (2x3).
// Warp tile 64x24: 4 m-frags x 3 n-frags of m16n8.
// ---------------------------------------------------------------------------
__device__ __forceinline__ void mma_tf32(float* d,
                                         float a0, float a1, float a2, float a3,
                                         float b0, float b1) {
    asm volatile(
        "mma.sync.aligned.m16n8k8.row.col.f32.tf32.tf32.f32 "
        "{%0,%1,%2,%3}, {%4,%5,%6,%7}, {%8,%9}, {%0,%1,%2,%3};"
        : "+f"(d[0]), "+f"(d[1]), "+f"(d[2]), "+f"(d[3])
        : "r"(__float_as_uint(a0)), "r"(__float_as_uint(a1)),
          "r"(__float_as_uint(a2)), "r"(__float_as_uint(a3)),
          "r"(__float_as_uint(b0)), "r"(__float_as_uint(b1)));
}

__global__ void __launch_bounds__(192, 2) gemm_kernel(const float* __restrict__ W3,
                                                      const float* __restrict__ b3,
                                                      float* __restrict__ out) {
    // As stride 136: bank = (8*ksub + pos) % 32, conflict-free fragment loads.
    __shared__ float As[KCHUNK][136];
    __shared__ float Bs[KCHUNK][72];

    int tid = threadIdx.x;
    int warp = tid >> 5, lane = tid & 31;
    int wm = warp / 3;        // 0..1  (m direction, 64 rows each)
    int wn = warp % 3;        // 0..2  (n direction, 24 cols each)
    int lk = lane & 3;        // k sub-index within fragment
    int ln = lane >> 2;       // row/col sub-index within fragment
    int row0 = blockIdx.x * 128;
    int n0 = blockIdx.y * 72;

    float acc[4][3][4];
#pragma unroll
    for (int mi = 0; mi < 4; mi++)
#pragma unroll
        for (int ni = 0; ni < 3; ni++)
#pragma unroll
            for (int q = 0; q < 4; q++) acc[mi][ni][q] = 0.0f;

    for (int ch = 0; ch < 2; ch++) {
        int kbase = ch * KCHUNK;
        // Fill As: [k][m], coalesced reads from H2^T (already tf32-rounded)
        for (int idx = tid; idx < KCHUNK * 128; idx += 192) {
            int k = idx >> 7, m = idx & 127;
            int kg = kbase + k;
            As[k][m] = (kg < KDIM) ? g_H2T[kg * BROWS + row0 + m] : 0.0f;
        }
        // Fill Bs: [k][n], convert W3 to tf32
        for (int idx = tid; idx < KCHUNK * 72; idx += 192) {
            int k = idx / 72, n = idx - k * 72;
            int kg = kbase + k;
            Bs[k][n] = (kg < KDIM) ? tf32_rna(W3[kg * NOUT + n0 + n]) : 0.0f;
        }
        __syncthreads();

#pragma unroll
        for (int ks = 0; ks < KCHUNK / 8; ks++) {
            int k0 = ks * 8;
            float bf[3][2];
#pragma unroll
            for (int ni = 0; ni < 3; ni++) {
                int n = wn * 24 + ni * 8 + ln;
                bf[ni][0] = Bs[k0 + lk][n];
                bf[ni][1] = Bs[k0 + lk + 4][n];
            }
#pragma unroll
            for (int mi = 0; mi < 4; mi++) {
                int m = wm * 64 + mi * 16 + ln;
                float a0 = As[k0 + lk][m];
                float a1 = As[k0 + lk][m + 8];
                float a2 = As[k0 + lk + 4][m];
                float a3 = As[k0 + lk + 4][m + 8];
#pragma unroll
                for (int ni = 0; ni < 3; ni++)
                    mma_tf32(acc[mi][ni], a0, a1, a2, a3, bf[ni][0], bf[ni][1]);
            }
        }
        __syncthreads();
    }

    // Epilogue: +b3, sigmoid, store. Grid divides exactly: no bounds checks.
#pragma unroll
    for (int mi = 0; mi < 4; mi++) {
        int r = row0 + wm * 64 + mi * 16 + ln;
#pragma unroll
        for (int ni = 0; ni < 3; ni++) {
            int n = n0 + wn * 24 + ni * 8 + 2 * lk;
            float bias0 = __ldg(&b3[n]);
            float bias1 = __ldg(&b3[n + 1]);
            out[r * OUT_STRIDE + n]           = sigmoid_fast(acc[mi][ni][0] + bias0);
            out[r * OUT_STRIDE + n + 1]       = sigmoid_fast(acc[mi][ni][1] + bias1);
            out[(r + 8) * OUT_STRIDE + n]     = sigmoid_fast(acc[mi][ni][2] + bias0);
            out[(r + 8) * OUT_STRIDE + n + 1] = sigmoid_fast(acc[mi][ni][3] + bias1);
        }
    }
}

// ---------------------------------------------------------------------------
// Kernel C: mirrored columns out[:, 1224:2193] from out[:, :1224]
// ---------------------------------------------------------------------------
__global__ void mirror_kernel(float* __restrict__ out) {
    int idx = blockIdx.x * blockDim.x + threadIdx.x;
    const int total = BROWS * (NMIR * NY);
    if (idx >= total) return;
    int row = idx / (NMIR * NY);
    int rem = idx - row * (NMIR * NY);
    int jj = rem / NY;
    int y = rem - jj * NY;
    const float* ro = out + row * OUT_STRIDE;
    float v;
    if (g_near[jj]) {
        v = ro[g_colnear[jj] * NY + y];
    } else {
        int c1 = g_col1[jj];
        float w = g_w[jj];
        v = w * ro[c1 * NY + y] + (1.0f - w) * ro[(c1 + 1) * NY + y];
    }
    out[row * OUT_STRIDE + NOUT + rem] = v;
}

// ---------------------------------------------------------------------------
extern "C" void kernel_launch(void* const* d_in, const int* in_sizes, int n_in,
                              void* d_out, int out_size) {
    const float* x  = (const float*)d_in[0];
    const float* W1 = (const float*)d_in[1];
    const float* b1 = (const float*)d_in[2];
    const float* W2 = (const float*)d_in[3];
    const float* b2 = (const float*)d_in[4];
    const float* W3 = (const float*)d_in[5];
    const float* b3 = (const float*)d_in[6];
    const float* xs = (const float*)d_in[7];
    float* out = (float*)d_out;

    prep_kernel<<<1, 64>>>(xs);
    mlp12_kernel<<<BROWS / 256, 256>>>(x, W1, b1, W2, b2);
    gemm_kernel<<<dim3(BROWS / 128, NOUT / 72), 192>>>(W3, b3, out);
    int total = BROWS * (NMIR * NY);
    mirror_kernel<<<(total + 255) / 256, 256>>>(out);
}

// round 2
// speedup vs baseline: 3.1136x; 3.1136x over previous
#include <cuda_runtime.h>
#include <cstdint>

#define TOTAL_LEN 0.078f
#define NGRID 129
#define NIN 72
#define NY 17
#define BROWS 65536
#define NOUT 1224        // 72*17
#define NMIROUT 969      // 57*17
#define OUT_STRIDE 2193  // 129*17
#define KDIM 100

// Table: 4096 intervals over [-8, 8], 4097 points, padded to 4160 (= 65*64)
#define NT_INT 4096
#define NT_PAD 4160
#define XMIN (-8.0f)
#define XSCALE 256.0f    // 4096 / 16

// Device scratch (no allocations allowed)
__device__ float g_tabH2[NT_PAD * KDIM];    // layer-2 activations per grid point
__device__ float g_table[NT_PAD * NOUT];    // xg table [point][1224]
__device__ int   g_s1[NMIROUT];
__device__ int   g_s2[NMIROUT];
__device__ float g_wm[NMIROUT];

__device__ __forceinline__ float sigmoid_fast(float z) {
    return 1.0f / (1.0f + __expf(-z));
}

// ---------------------------------------------------------------------------
// Kernel P: per-mirror-element interpolation params (969 outputs)
// ---------------------------------------------------------------------------
__global__ void prep_kernel(const float* __restrict__ xs) {
    __shared__ float sxs[NGRID];
    int t = threadIdx.x;
    for (int i = t; i < NGRID; i += blockDim.x) sxs[i] = xs[i];
    __syncthreads();
    if (t < NMIROUT) {
        int jj = t / NY;
        int y  = t - jj * NY;
        float x_pos = TOTAL_LEN - sxs[NIN + jj];
        bool near = (TOTAL_LEN - x_pos) < 0.02f;
        if (near) {
            int best = 0; float bd = fabsf(x_pos - sxs[0]);
            for (int i = 1; i < NGRID; i++) {
                float d = fabsf(x_pos - sxs[i]);
                if (d < bd) { bd = d; best = i; }
            }
            if (best > NIN - 1) best = NIN - 1;
            g_s1[t] = best * NY + y;
            g_s2[t] = best * NY + y;
            g_wm[t] = 1.0f;
        } else {
            int cnt = 0;
            for (int i = 0; i < NGRID; i++) cnt += (sxs[i] <= x_pos) ? 1 : 0;
            int c1 = cnt - 1;
            if (c1 < 0) c1 = 0;
            if (c1 > NIN - 2) c1 = NIN - 2;
            g_s1[t] = c1 * NY + y;
            g_s2[t] = (c1 + 1) * NY + y;
            g_wm[t] = (sxs[c1 + 1] - x_pos) / (sxs[c1 + 1] - sxs[c1]);
        }
    }
}

// ---------------------------------------------------------------------------
// Kernel A: layers 1+2 at the 4160 table grid points -> g_tabH2[p][k]
// ---------------------------------------------------------------------------
__global__ void h2grid_kernel(const float* __restrict__ W1, const float* __restrict__ b1,
                              const float* __restrict__ W2, const float* __restrict__ b2) {
    __shared__ float sW1[10], sb1[10], sW2[1000], sb2[100];
    int t = threadIdx.x;
    if (t < 10) { sW1[t] = W1[t]; sb1[t] = b1[t]; }
    for (int i = t; i < 1000; i += blockDim.x) sW2[i] = W2[i];
    if (t < 100) sb2[t] = b2[t];
    __syncthreads();

    int p = blockIdx.x * blockDim.x + t;
    if (p >= NT_PAD) return;
    float xv = XMIN + (float)p * (1.0f / XSCALE);
    float h1[10];
#pragma unroll
    for (int j = 0; j < 10; j++)
        h1[j] = sigmoid_fast(fmaf(xv, sW1[j], sb1[j]));
#pragma unroll 4
    for (int i = 0; i < 100; i++) {
        float s = sb2[i];
#pragma unroll
        for (int j = 0; j < 10; j++) s = fmaf(h1[j], sW2[j * 100 + i], s);
        g_tabH2[p * KDIM + i] = sigmoid_fast(s);
    }
}

// ---------------------------------------------------------------------------
// Kernel B: table = sigmoid(H2grid @ W3 + b3)   [4160 x 100] @ [100 x 1224]
// fp32 SIMT GEMM: block tile 64x72, 256 threads, 18 acc each (2 rows x 9 cols)
// ---------------------------------------------------------------------------
#define TB_KC 50
__global__ void __launch_bounds__(256) table_gemm_kernel(const float* __restrict__ W3,
                                                         const float* __restrict__ b3) {
    __shared__ float As[64][101];     // all K=100, padded stride (conflict-free)
    __shared__ float Bs[TB_KC][72];

    int tid = threadIdx.x;
    int tm = tid & 31;                // lane -> row pair {tm, tm+32}
    int tn = tid >> 5;                // warp id -> 9-col group (uniform per warp)
    int p0 = blockIdx.x * 64;
    int n0 = blockIdx.y * 72;

    // Load full A tile (64 x 100)
    for (int idx = tid; idx < 64 * 100; idx += 256) {
        int r = idx / 100, k = idx - r * 100;
        As[r][k] = g_tabH2[(p0 + r) * KDIM + k];
    }

    float acc[2][9];
#pragma unroll
    for (int a = 0; a < 2; a++)
#pragma unroll
        for (int j = 0; j < 9; j++) acc[a][j] = 0.0f;

    for (int ch = 0; ch < 2; ch++) {
        int kb = ch * TB_KC;
        __syncthreads();
        for (int idx = tid; idx < TB_KC * 72; idx += 256) {
            int k = idx / 72, n = idx - k * 72;
            Bs[k][n] = W3[(kb + k) * NOUT + n0 + n];
        }
        __syncthreads();
#pragma unroll 5
        for (int k = 0; k < TB_KC; k++) {
            float a0 = As[tm][kb + k];
            float a1 = As[tm + 32][kb + k];
#pragma unroll
            for (int j = 0; j < 9; j++) {
                float bv = Bs[k][tn * 9 + j];   // warp-uniform broadcast
                acc[0][j] = fmaf(a0, bv, acc[0][j]);
                acc[1][j] = fmaf(a1, bv, acc[1][j]);
            }
        }
    }

#pragma unroll
    for (int j = 0; j < 9; j++) {
        int col = n0 + tn * 9 + j;
        float bias = __ldg(&b3[col]);
        g_table[(p0 + tm) * NOUT + col]      = sigmoid_fast(acc[0][j] + bias);
        g_table[(p0 + tm + 32) * NOUT + col] = sigmoid_fast(acc[1][j] + bias);
    }
}

// ---------------------------------------------------------------------------
// Kernel C: evaluate. One block per sample. Lerp table rows -> out[:, :1224],
// stash xg in smem, then mirror -> out[:, 1224:2193].
// ---------------------------------------------------------------------------
__global__ void __launch_bounds__(256) eval_kernel(const float* __restrict__ x,
                                                   float* __restrict__ out) {
    __shared__ float xg[NOUT];
    int b = blockIdx.x;
    int tid = threadIdx.x;

    float xv = x[b];
    xv = fminf(fmaxf(xv, XMIN), -XMIN);
    float u = (xv - XMIN) * XSCALE;          // [0, 4096]
    int i = (int)u;
    if (i > NT_INT - 1) i = NT_INT - 1;
    float f = u - (float)i;

    const float* t0 = g_table + (size_t)i * NOUT;
    const float* t1 = t0 + NOUT;
    float* orow = out + (size_t)b * OUT_STRIDE;

#pragma unroll
    for (int c = tid; c < NOUT; c += 256) {
        float v0 = __ldg(&t0[c]);
        float v1 = __ldg(&t1[c]);
        float v = fmaf(f, v1 - v0, v0);
        orow[c] = v;
        xg[c] = v;
    }
    __syncthreads();

#pragma unroll
    for (int m = tid; m < NMIROUT; m += 256) {
        float a = xg[__ldg(&g_s1[m])];
        float bb = xg[__ldg(&g_s2[m])];
        float w = __ldg(&g_wm[m]);
        orow[NOUT + m] = fmaf(w, a - bb, bb);
    }
}

// ---------------------------------------------------------------------------
extern "C" void kernel_launch(void* const* d_in, const int* in_sizes, int n_in,
                              void* d_out, int out_size) {
    const float* x  = (const float*)d_in[0];
    const float* W1 = (const float*)d_in[1];
    const float* b1 = (const float*)d_in[2];
    const float* W2 = (const float*)d_in[3];
    const float* b2 = (const float*)d_in[4];
    const float* W3 = (const float*)d_in[5];
    const float* b3 = (const float*)d_in[6];
    const float* xs = (const float*)d_in[7];
    float* out = (float*)d_out;

    prep_kernel<<<1, 1024>>>(xs);
    h2grid_kernel<<<(NT_PAD + 255) / 256, 256>>>(W1, b1, W2, b2);
    table_gemm_kernel<<<dim3(NT_PAD / 64, NOUT / 72), 256>>>(W3, b3);
    eval_kernel<<<BROWS, 256>>>(x, out);
}